// round 7
// baseline (speedup 1.0000x reference)
#include <cuda_runtime.h>
#include <math.h>
#include <stdint.h>

// Problem constants
#define BB   2
#define TT   4096
#define CC   768
#define HH   12
#define HD   64
#define MM   (BB*TT)        // 8192 rows
#define NQKV (3*CC)         // 2304

// Scratch (no cudaMalloc allowed)
__device__ float g_qkv[(size_t)MM * NQKV];
__device__ float g_y[(size_t)MM * CC];

// ----------------------------------------------------------------------------
// TF32 helpers
// ----------------------------------------------------------------------------
__device__ __forceinline__ float tf32r(float x) {
    uint32_t r;
    asm("cvt.rna.tf32.f32 %0, %1;" : "=r"(r) : "f"(x));
    return __uint_as_float(r);
}

__device__ __forceinline__ void mma_tf32(float* d, const uint32_t* a,
                                         uint32_t b0, uint32_t b1) {
    asm volatile(
        "mma.sync.aligned.m16n8k8.row.col.f32.tf32.tf32.f32 "
        "{%0,%1,%2,%3}, {%4,%5,%6,%7}, {%8,%9}, {%0,%1,%2,%3};\n"
        : "+f"(d[0]), "+f"(d[1]), "+f"(d[2]), "+f"(d[3])
        : "r"(a[0]), "r"(a[1]), "r"(a[2]), "r"(a[3]), "r"(b0), "r"(b1));
}

// ----------------------------------------------------------------------------
// TF32 tensor-core GEMM: C[M,N] = A[M,K] @ B[K,N] + bias[N]
// Block 128x128, BK=16, 8 warps (2m x 4n). Stride 136: fragment loads
// conflict-free (bank = 8*ql + quad, all distinct mod 32).
// ----------------------------------------------------------------------------
__global__ __launch_bounds__(256)
void gemm_tf32_bias(const float* __restrict__ A, const float* __restrict__ Bm,
                    const float* __restrict__ bias, float* __restrict__ Cm,
                    int M, int N, int K)
{
    __shared__ float As[16][136];   // k-major A tile
    __shared__ float Bs[16][136];   // k-major B tile

    const int tid  = threadIdx.x;
    const int lane = tid & 31, warp = tid >> 5;
    const int quad = lane >> 2, ql = lane & 3;
    const int wm = (warp & 1) * 64;
    const int wn = (warp >> 1) * 32;
    const int cm = blockIdx.y * 128, cn = blockIdx.x * 128;

    const int arow = tid >> 2, acol = (tid & 3) << 2;
    const int brow = tid >> 5, bcol = (tid & 31) << 2;

    const float* Ab = A + (size_t)cm * K;
    const float* Bb = Bm + cn;

    float acc[4][4][4];
#pragma unroll
    for (int mt = 0; mt < 4; ++mt)
#pragma unroll
        for (int nt = 0; nt < 4; ++nt)
#pragma unroll
            for (int f = 0; f < 4; ++f) acc[mt][nt][f] = 0.f;

    float4 pa0 = *(const float4*)(Ab + (size_t)arow * K + acol);
    float4 pa1 = *(const float4*)(Ab + (size_t)(arow + 64) * K + acol);
    float4 pb0 = *(const float4*)(Bb + (size_t)brow * N + bcol);
    float4 pb1 = *(const float4*)(Bb + (size_t)(brow + 8) * N + bcol);

    const int NK = K >> 4;
    for (int kt = 0; kt < NK; ++kt) {
        As[acol + 0][arow]      = tf32r(pa0.x);
        As[acol + 1][arow]      = tf32r(pa0.y);
        As[acol + 2][arow]      = tf32r(pa0.z);
        As[acol + 3][arow]      = tf32r(pa0.w);
        As[acol + 0][arow + 64] = tf32r(pa1.x);
        As[acol + 1][arow + 64] = tf32r(pa1.y);
        As[acol + 2][arow + 64] = tf32r(pa1.z);
        As[acol + 3][arow + 64] = tf32r(pa1.w);
        float4 tb;
        tb.x = tf32r(pb0.x); tb.y = tf32r(pb0.y);
        tb.z = tf32r(pb0.z); tb.w = tf32r(pb0.w);
        *(float4*)&Bs[brow][bcol] = tb;
        tb.x = tf32r(pb1.x); tb.y = tf32r(pb1.y);
        tb.z = tf32r(pb1.z); tb.w = tf32r(pb1.w);
        *(float4*)&Bs[brow + 8][bcol] = tb;
        __syncthreads();

        if (kt + 1 < NK) {
            const int k0 = (kt + 1) << 4;
            pa0 = *(const float4*)(Ab + (size_t)arow * K + k0 + acol);
            pa1 = *(const float4*)(Ab + (size_t)(arow + 64) * K + k0 + acol);
            pb0 = *(const float4*)(Bb + (size_t)(k0 + brow) * N + bcol);
            pb1 = *(const float4*)(Bb + (size_t)(k0 + brow + 8) * N + bcol);
        }

#pragma unroll
        for (int ks = 0; ks < 2; ++ks) {
            const int kk = ks * 8;
            uint32_t af[4][4];
#pragma unroll
            for (int mt = 0; mt < 4; ++mt) {
                const int mb = wm + mt * 16;
                af[mt][0] = __float_as_uint(As[kk + ql][mb + quad]);
                af[mt][1] = __float_as_uint(As[kk + ql][mb + quad + 8]);
                af[mt][2] = __float_as_uint(As[kk + ql + 4][mb + quad]);
                af[mt][3] = __float_as_uint(As[kk + ql + 4][mb + quad + 8]);
            }
#pragma unroll
            for (int nt = 0; nt < 4; ++nt) {
                const uint32_t b0 = __float_as_uint(Bs[kk + ql][wn + nt * 8 + quad]);
                const uint32_t b1 = __float_as_uint(Bs[kk + ql + 4][wn + nt * 8 + quad]);
#pragma unroll
                for (int mt = 0; mt < 4; ++mt)
                    mma_tf32(acc[mt][nt], af[mt], b0, b1);
            }
        }
        __syncthreads();
    }

#pragma unroll
    for (int mt = 0; mt < 4; ++mt) {
        const int r0 = cm + wm + mt * 16 + quad;
#pragma unroll
        for (int nt = 0; nt < 4; ++nt) {
            const int c = cn + wn + nt * 8 + ql * 2;
            const float bx = bias[c], by = bias[c + 1];
            float2 w;
            w.x = acc[mt][nt][0] + bx; w.y = acc[mt][nt][1] + by;
            *(float2*)(Cm + (size_t)r0 * N + c) = w;
            w.x = acc[mt][nt][2] + bx; w.y = acc[mt][nt][3] + by;
            *(float2*)(Cm + (size_t)(r0 + 8) * N + c) = w;
        }
    }
}

// ----------------------------------------------------------------------------
// Flash attention, tf32 tensor cores, LDS-optimized layouts:
//  Ks : [token][d-interleaved]  -> B-frag pair = one LDS.64, conflict-free
//  Vt : [d][token-ilv ^ swz(d)] -> B-frag pair = one LDS.64, conflict-free
//  Ps : [row][col-interleaved]  -> A-frag pair = one LDS.64, conflict-free
// stride 72 everywhere; smem = (128+64+64)*72*4 = 73728 B.
// Interleave within 8-group: c -> (c<4) ? 2c : 2c-7  (pairs c, c+4 adjacent)
// ----------------------------------------------------------------------------
#define FS 72
#define FA_SMEM_BYTES ((128 + 64 + 64) * FS * sizeof(float))

__global__ __launch_bounds__(256)
void flash_attn_tf32_kernel(const float* __restrict__ qkv, float* __restrict__ y)
{
    extern __shared__ float sm[];
    float* Qs = sm;                    // [128][FS], reused as Ps (interleaved)
    float* Ks = sm + 128 * FS;         // [64][FS], col-interleaved
    float* Vt = Ks + 64 * FS;          // [64][FS], transposed + swizzled

    const int tid  = threadIdx.x;
    const int warp = tid >> 5;
    const int lane = tid & 31;
    const int quad = lane >> 2;
    const int ql   = lane & 3;
    const int qb = blockIdx.x;
    const int h  = blockIdx.y;
    const int b  = blockIdx.z;
    const int q0 = qb * 128;
    const size_t rowBase = (size_t)b * TT;
    const int qOff = h * HD, kOff = CC + h * HD, vOff = 2 * CC + h * HD;

    // ---- load Q tile (128 x 64), plain layout (read once into regs) ----
#pragma unroll
    for (int p = 0; p < 8; ++p) {
        const int f4 = tid + 256 * p;
        const int r = f4 >> 4, c = (f4 & 15) << 2;
        const float4 v = *(const float4*)(qkv + (rowBase + q0 + r) * NQKV + qOff + c);
        Qs[r * FS + c + 0] = tf32r(v.x);
        Qs[r * FS + c + 1] = tf32r(v.y);
        Qs[r * FS + c + 2] = tf32r(v.z);
        Qs[r * FS + c + 3] = tf32r(v.w);
    }
    __syncthreads();

    const int rloc = warp * 16 + quad;
    uint32_t qa[8][4];
#pragma unroll
    for (int ks = 0; ks < 8; ++ks) {
        const int c = ks * 8 + ql;
        qa[ks][0] = __float_as_uint(Qs[rloc * FS + c]);
        qa[ks][1] = __float_as_uint(Qs[(rloc + 8) * FS + c]);
        qa[ks][2] = __float_as_uint(Qs[rloc * FS + c + 4]);
        qa[ks][3] = __float_as_uint(Qs[(rloc + 8) * FS + c + 4]);
    }

    float m0 = -INFINITY, m1 = -INFINITY, l0 = 0.f, l1 = 0.f;
    float o[8][4];
#pragma unroll
    for (int t = 0; t < 8; ++t) { o[t][0] = o[t][1] = o[t][2] = o[t][3] = 0.f; }

    const int qrow0 = q0 + warp * 16 + quad;
    const int qrow1 = qrow0 + 8;
    const float C2 = 0.18033688011112042f;   // log2(e) / sqrt(64)

    // P-write interleaved column positions for cols 2ql, 2ql+1 (within 8-group)
    const int c0i = 2 * ql, c1i = 2 * ql + 1;
    const int plo = (c0i < 4) ? 2 * c0i : 2 * c0i - 7;
    const int phi = (c1i < 4) ? 2 * c1i : 2 * c1i - 7;

    const int nkt = (q0 >> 6) + 2;
    for (int kt = 0; kt < nkt; ++kt) {
        const int k0 = kt << 6;
        __syncthreads();
        // ---- load K (col-interleaved) and V (transposed+swizzled) ----
#pragma unroll
        for (int p = 0; p < 4; ++p) {
            const int f4 = tid + 256 * p;
            const int r = f4 >> 4;            // token in tile (0..63)
            const int c = (f4 & 15) << 2;     // d base (0,4,...,60)
            const size_t g = (rowBase + k0 + r) * NQKV;
            const float4 kv = *(const float4*)(qkv + g + kOff + c);
            // K interleave: group (c>>3)*8, pos = 2i + (c&4 ? 1 : 0)
            const int kbase = r * FS + ((c >> 3) << 3) + ((c & 4) ? 1 : 0);
            Ks[kbase + 0] = tf32r(kv.x);
            Ks[kbase + 2] = tf32r(kv.y);
            Ks[kbase + 4] = tf32r(kv.z);
            Ks[kbase + 6] = tf32r(kv.w);
            const float4 vv = *(const float4*)(qkv + g + vOff + c);
            // V transpose: token r -> interleaved pos, XOR-swizzled by d-group
            const int rr = r & 7;
            const int ip = ((r >> 3) << 3) + ((rr < 4) ? 2 * rr : 2 * rr - 7);
            const int vpos = ip ^ (2 * ((c >> 2) & 7));   // same for d=c..c+3
            Vt[(c + 0) * FS + vpos] = tf32r(vv.x);
            Vt[(c + 1) * FS + vpos] = tf32r(vv.y);
            Vt[(c + 2) * FS + vpos] = tf32r(vv.z);
            Vt[(c + 3) * FS + vpos] = tf32r(vv.w);
        }
        __syncthreads();

        // ---- S = Q K^T ----
        float sacc[8][4];
#pragma unroll
        for (int t = 0; t < 8; ++t) { sacc[t][0] = sacc[t][1] = sacc[t][2] = sacc[t][3] = 0.f; }
#pragma unroll
        for (int ks = 0; ks < 8; ++ks) {
#pragma unroll
            for (int t = 0; t < 8; ++t) {
                const float2 kb = *(const float2*)&Ks[(t * 8 + quad) * FS + ks * 8 + 2 * ql];
                mma_tf32(sacc[t], qa[ks],
                         __float_as_uint(kb.x), __float_as_uint(kb.y));
            }
        }

        // ---- scale + causal mask + row max ----
        float rm0 = -INFINITY, rm1 = -INFINITY;
#pragma unroll
        for (int t = 0; t < 8; ++t) {
            const int gc = k0 + t * 8 + ql * 2;
            float v0 = sacc[t][0] * C2; if (gc     > qrow0) v0 = -INFINITY;
            float v1 = sacc[t][1] * C2; if (gc + 1 > qrow0) v1 = -INFINITY;
            float v2 = sacc[t][2] * C2; if (gc     > qrow1) v2 = -INFINITY;
            float v3 = sacc[t][3] * C2; if (gc + 1 > qrow1) v3 = -INFINITY;
            sacc[t][0] = v0; sacc[t][1] = v1; sacc[t][2] = v2; sacc[t][3] = v3;
            rm0 = fmaxf(rm0, fmaxf(v0, v1));
            rm1 = fmaxf(rm1, fmaxf(v2, v3));
        }
        rm0 = fmaxf(rm0, __shfl_xor_sync(0xffffffffu, rm0, 1));
        rm0 = fmaxf(rm0, __shfl_xor_sync(0xffffffffu, rm0, 2));
        rm1 = fmaxf(rm1, __shfl_xor_sync(0xffffffffu, rm1, 1));
        rm1 = fmaxf(rm1, __shfl_xor_sync(0xffffffffu, rm1, 2));
        const float mn0 = fmaxf(m0, rm0);
        const float mn1 = fmaxf(m1, rm1);
        const float al0 = exp2f(m0 - mn0);
        const float al1 = exp2f(m1 - mn1);

        // ---- exp, P write (interleaved), O rescale ----
        float* Ps = Qs;
        float sum0 = 0.f, sum1 = 0.f;
#pragma unroll
        for (int t = 0; t < 8; ++t) {
            const float p0 = exp2f(sacc[t][0] - mn0);
            const float p1 = exp2f(sacc[t][1] - mn0);
            const float p2 = exp2f(sacc[t][2] - mn1);
            const float p3 = exp2f(sacc[t][3] - mn1);
            sum0 += p0 + p1; sum1 += p2 + p3;
            o[t][0] *= al0; o[t][1] *= al0; o[t][2] *= al1; o[t][3] *= al1;
            const int pg = t * 8;
            Ps[rloc * FS + pg + plo]       = tf32r(p0);
            Ps[rloc * FS + pg + phi]       = tf32r(p1);
            Ps[(rloc + 8) * FS + pg + plo] = tf32r(p2);
            Ps[(rloc + 8) * FS + pg + phi] = tf32r(p3);
        }
        sum0 += __shfl_xor_sync(0xffffffffu, sum0, 1);
        sum0 += __shfl_xor_sync(0xffffffffu, sum0, 2);
        sum1 += __shfl_xor_sync(0xffffffffu, sum1, 1);
        sum1 += __shfl_xor_sync(0xffffffffu, sum1, 2);
        l0 = l0 * al0 + sum0;
        l1 = l1 * al1 + sum1;
        m0 = mn0; m1 = mn1;
        __syncwarp();   // P rows are warp-private

        // ---- O += P V ----
#pragma unroll
        for (int ks = 0; ks < 8; ++ks) {
            const float2 pl = *(const float2*)&Ps[rloc * FS + ks * 8 + 2 * ql];
            const float2 ph = *(const float2*)&Ps[(rloc + 8) * FS + ks * 8 + 2 * ql];
            uint32_t pa[4];
            pa[0] = __float_as_uint(pl.x);
            pa[1] = __float_as_uint(ph.x);
            pa[2] = __float_as_uint(pl.y);
            pa[3] = __float_as_uint(ph.y);
#pragma unroll
            for (int t = 0; t < 8; ++t) {
                const int d = t * 8 + quad;
                const float2 vb = *(const float2*)&Vt[d * FS +
                                   ((ks * 8 + 2 * ql) ^ (2 * ((d >> 2) & 7)))];
                mma_tf32(o[t], pa,
                         __float_as_uint(vb.x), __float_as_uint(vb.y));
            }
        }
        __syncwarp();
    }

    // ---- epilogue ----
    const float inv0 = 1.f / l0;
    const float inv1 = 1.f / l1;
#pragma unroll
    for (int t = 0; t < 8; ++t) {
        const int col = h * HD + t * 8 + ql * 2;
        float2 w;
        w.x = o[t][0] * inv0; w.y = o[t][1] * inv0;
        *(float2*)(y + (rowBase + qrow0) * CC + col) = w;
        w.x = o[t][2] * inv1; w.y = o[t][3] * inv1;
        *(float2*)(y + (rowBase + qrow1) * CC + col) = w;
    }
}

// ----------------------------------------------------------------------------
extern "C" void kernel_launch(void* const* d_in, const int* in_sizes, int n_in,
                              void* d_out, int out_size)
{
    const float *x = nullptr, *w_attn = nullptr, *b_attn = nullptr,
                *w_proj = nullptr, *b_proj = nullptr;
    for (int i = 0; i < n_in; ++i) {
        const int s = in_sizes[i];
        const float* p = (const float*)d_in[i];
        if      (s == MM * CC)   x      = p;
        else if (s == CC * NQKV) w_attn = p;
        else if (s == NQKV)      b_attn = p;
        else if (s == CC * CC)   w_proj = p;
        else if (s == CC)        b_proj = p;
    }
    float* out = (float*)d_out;

    float *qkv = nullptr, *y = nullptr;
    cudaGetSymbolAddress((void**)&qkv, g_qkv);
    cudaGetSymbolAddress((void**)&y, g_y);

    cudaFuncSetAttribute(flash_attn_tf32_kernel,
                         cudaFuncAttributeMaxDynamicSharedMemorySize,
                         (int)FA_SMEM_BYTES);

    dim3 blk(256);
    gemm_tf32_bias<<<dim3(NQKV / 128, MM / 128), blk>>>(
        x, w_attn, b_attn, qkv, MM, NQKV, CC);
    flash_attn_tf32_kernel<<<dim3(TT / 128, HH, BB), blk, FA_SMEM_BYTES>>>(qkv, y);
    gemm_tf32_bias<<<dim3(CC / 128, MM / 128), blk>>>(
        y, w_proj, b_proj, out, MM, CC, CC);
}

// round 9
// speedup vs baseline: 1.2632x; 1.2632x over previous
#include <cuda_runtime.h>
#include <math.h>
#include <stdint.h>

// Problem constants
#define BB   2
#define TT   4096
#define CC   768
#define HH   12
#define HD   64
#define MM   (BB*TT)        // 8192 rows
#define NQKV (3*CC)         // 2304

// Scratch (no cudaMalloc allowed)
__device__ float g_qkv[(size_t)MM * NQKV];
__device__ float g_y[(size_t)MM * CC];

// ----------------------------------------------------------------------------
// TF32 helpers
// ----------------------------------------------------------------------------
__device__ __forceinline__ float tf32r(float x) {
    uint32_t r;
    asm("cvt.rna.tf32.f32 %0, %1;" : "=r"(r) : "f"(x));
    return __uint_as_float(r);
}

__device__ __forceinline__ void mma_tf32(float* d, const uint32_t* a,
                                         uint32_t b0, uint32_t b1) {
    asm volatile(
        "mma.sync.aligned.m16n8k8.row.col.f32.tf32.tf32.f32 "
        "{%0,%1,%2,%3}, {%4,%5,%6,%7}, {%8,%9}, {%0,%1,%2,%3};\n"
        : "+f"(d[0]), "+f"(d[1]), "+f"(d[2]), "+f"(d[3])
        : "r"(a[0]), "r"(a[1]), "r"(a[2]), "r"(a[3]), "r"(b0), "r"(b1));
}

// ----------------------------------------------------------------------------
// TF32 tensor-core GEMM (R7-measured: 248us QKV). Stride 136, conflict-free
// fragment loads. Block 128x128, BK=16, 8 warps (2m x 4n).
// ----------------------------------------------------------------------------
__global__ __launch_bounds__(256)
void gemm_tf32_bias(const float* __restrict__ A, const float* __restrict__ Bm,
                    const float* __restrict__ bias, float* __restrict__ Cm,
                    int M, int N, int K)
{
    __shared__ float As[16][136];
    __shared__ float Bs[16][136];

    const int tid  = threadIdx.x;
    const int lane = tid & 31, warp = tid >> 5;
    const int quad = lane >> 2, ql = lane & 3;
    const int wm = (warp & 1) * 64;
    const int wn = (warp >> 1) * 32;
    const int cm = blockIdx.y * 128, cn = blockIdx.x * 128;

    const int arow = tid >> 2, acol = (tid & 3) << 2;
    const int brow = tid >> 5, bcol = (tid & 31) << 2;

    const float* Ab = A + (size_t)cm * K;
    const float* Bb = Bm + cn;

    float acc[4][4][4];
#pragma unroll
    for (int mt = 0; mt < 4; ++mt)
#pragma unroll
        for (int nt = 0; nt < 4; ++nt)
#pragma unroll
            for (int f = 0; f < 4; ++f) acc[mt][nt][f] = 0.f;

    float4 pa0 = *(const float4*)(Ab + (size_t)arow * K + acol);
    float4 pa1 = *(const float4*)(Ab + (size_t)(arow + 64) * K + acol);
    float4 pb0 = *(const float4*)(Bb + (size_t)brow * N + bcol);
    float4 pb1 = *(const float4*)(Bb + (size_t)(brow + 8) * N + bcol);

    const int NK = K >> 4;
    for (int kt = 0; kt < NK; ++kt) {
        As[acol + 0][arow]      = tf32r(pa0.x);
        As[acol + 1][arow]      = tf32r(pa0.y);
        As[acol + 2][arow]      = tf32r(pa0.z);
        As[acol + 3][arow]      = tf32r(pa0.w);
        As[acol + 0][arow + 64] = tf32r(pa1.x);
        As[acol + 1][arow + 64] = tf32r(pa1.y);
        As[acol + 2][arow + 64] = tf32r(pa1.z);
        As[acol + 3][arow + 64] = tf32r(pa1.w);
        float4 tb;
        tb.x = tf32r(pb0.x); tb.y = tf32r(pb0.y);
        tb.z = tf32r(pb0.z); tb.w = tf32r(pb0.w);
        *(float4*)&Bs[brow][bcol] = tb;
        tb.x = tf32r(pb1.x); tb.y = tf32r(pb1.y);
        tb.z = tf32r(pb1.z); tb.w = tf32r(pb1.w);
        *(float4*)&Bs[brow + 8][bcol] = tb;
        __syncthreads();

        if (kt + 1 < NK) {
            const int k0 = (kt + 1) << 4;
            pa0 = *(const float4*)(Ab + (size_t)arow * K + k0 + acol);
            pa1 = *(const float4*)(Ab + (size_t)(arow + 64) * K + k0 + acol);
            pb0 = *(const float4*)(Bb + (size_t)(k0 + brow) * N + bcol);
            pb1 = *(const float4*)(Bb + (size_t)(k0 + brow + 8) * N + bcol);
        }

#pragma unroll
        for (int ks = 0; ks < 2; ++ks) {
            const int kk = ks * 8;
            uint32_t af[4][4];
#pragma unroll
            for (int mt = 0; mt < 4; ++mt) {
                const int mb = wm + mt * 16;
                af[mt][0] = __float_as_uint(As[kk + ql][mb + quad]);
                af[mt][1] = __float_as_uint(As[kk + ql][mb + quad + 8]);
                af[mt][2] = __float_as_uint(As[kk + ql + 4][mb + quad]);
                af[mt][3] = __float_as_uint(As[kk + ql + 4][mb + quad + 8]);
            }
#pragma unroll
            for (int nt = 0; nt < 4; ++nt) {
                const uint32_t b0 = __float_as_uint(Bs[kk + ql][wn + nt * 8 + quad]);
                const uint32_t b1 = __float_as_uint(Bs[kk + ql + 4][wn + nt * 8 + quad]);
#pragma unroll
                for (int mt = 0; mt < 4; ++mt)
                    mma_tf32(acc[mt][nt], af[mt], b0, b1);
            }
        }
        __syncthreads();
    }

#pragma unroll
    for (int mt = 0; mt < 4; ++mt) {
        const int r0 = cm + wm + mt * 16 + quad;
#pragma unroll
        for (int nt = 0; nt < 4; ++nt) {
            const int c = cn + wn + nt * 8 + ql * 2;
            const float bx = bias[c], by = bias[c + 1];
            float2 w;
            w.x = acc[mt][nt][0] + bx; w.y = acc[mt][nt][1] + by;
            *(float2*)(Cm + (size_t)r0 * N + c) = w;
            w.x = acc[mt][nt][2] + bx; w.y = acc[mt][nt][3] + by;
            *(float2*)(Cm + (size_t)(r0 + 8) * N + c) = w;
        }
    }
}

// ----------------------------------------------------------------------------
// Flash attention v2: warp m-tile 32 (8 warps -> 256 q-rows per CTA).
// Halves K/V-fragment crossbar traffic per MMA vs the 16-row version.
// Layouts (plain row-major, R4-style):
//  Qs [256][68]  Ps [256][68]  Ks [64][68]  Vs [64][72]
//  K/Q/P frag reads: bank = 4*quad + ql + c  -> conflict-free (stride 68)
//  V   frag reads: bank = 8*ql + quad + c    -> conflict-free (stride 72)
// smem total = (256+256)*68*4 + 64*68*4 + 64*72*4 = 175104 B -> 1 CTA/SM.
// ----------------------------------------------------------------------------
#define FSK 68
#define FSV 72
#define FA_SMEM_BYTES ((512 * FSK + 64 * FSK + 64 * FSV) * sizeof(float))

__global__ __launch_bounds__(256, 1)
void flash_attn_tf32_kernel(const float* __restrict__ qkv, float* __restrict__ y)
{
    extern __shared__ float sm[];
    float* Qs = sm;                       // [256][68]
    float* Ps = Qs + 256 * FSK;           // [256][68]
    float* Ks = Ps + 256 * FSK;           // [64][68]
    float* Vs = Ks + 64 * FSK;            // [64][72]

    const int tid  = threadIdx.x;
    const int warp = tid >> 5;
    const int lane = tid & 31;
    const int quad = lane >> 2;
    const int ql   = lane & 3;
    const int h  = blockIdx.y;
    const int b  = blockIdx.z;
    const int q0 = blockIdx.x * 256;
    const size_t rowBase = (size_t)b * TT;
    const int qOff = h * HD, kOff = CC + h * HD, vOff = 2 * CC + h * HD;

    const int rq = warp * 32 + quad;      // local base row (mt0 low half)

    // ---- load Q tile (256 x 64) ----
#pragma unroll
    for (int p = 0; p < 16; ++p) {
        const int f4 = tid + 256 * p;
        const int r = f4 >> 4, c = (f4 & 15) << 2;
        const float4 v = *(const float4*)(qkv + (rowBase + q0 + r) * NQKV + qOff + c);
        Qs[r * FSK + c + 0] = tf32r(v.x);
        Qs[r * FSK + c + 1] = tf32r(v.y);
        Qs[r * FSK + c + 2] = tf32r(v.z);
        Qs[r * FSK + c + 3] = tf32r(v.w);
    }
    __syncthreads();

    // ---- mt0 Q fragments in registers (rows rq, rq+8) ----
    uint32_t qa0[8][4];
#pragma unroll
    for (int ks = 0; ks < 8; ++ks) {
        const int c = ks * 8 + ql;
        qa0[ks][0] = __float_as_uint(Qs[rq * FSK + c]);
        qa0[ks][1] = __float_as_uint(Qs[(rq + 8) * FSK + c]);
        qa0[ks][2] = __float_as_uint(Qs[rq * FSK + c + 4]);
        qa0[ks][3] = __float_as_uint(Qs[(rq + 8) * FSK + c + 4]);
    }

    // softmax state for 4 rows: [mt*2 + half], rows qrow[i]
    float m[4], l[4];
#pragma unroll
    for (int i = 0; i < 4; ++i) { m[i] = -INFINITY; l[i] = 0.f; }
    int qrow[4];
    qrow[0] = q0 + rq;       qrow[1] = q0 + rq + 8;
    qrow[2] = q0 + rq + 16;  qrow[3] = q0 + rq + 24;
    const int wmax = q0 + warp * 32 + 31;   // warp's max q row

    float o[2][8][4];
#pragma unroll
    for (int mt = 0; mt < 2; ++mt)
#pragma unroll
        for (int t = 0; t < 8; ++t)
            o[mt][t][0] = o[mt][t][1] = o[mt][t][2] = o[mt][t][3] = 0.f;

    const float C2 = 0.18033688011112042f;   // log2(e) / sqrt(64)

    const int nkt = (q0 >> 6) + 4;
    for (int kt = 0; kt < nkt; ++kt) {
        const int k0 = kt << 6;
        __syncthreads();
        // ---- load K (stride 68) and V (stride 72) tiles ----
#pragma unroll
        for (int p = 0; p < 4; ++p) {
            const int f4 = tid + 256 * p;
            const int r = f4 >> 4, c = (f4 & 15) << 2;
            const size_t g = (rowBase + k0 + r) * NQKV;
            const float4 kv = *(const float4*)(qkv + g + kOff + c);
            Ks[r * FSK + c + 0] = tf32r(kv.x);
            Ks[r * FSK + c + 1] = tf32r(kv.y);
            Ks[r * FSK + c + 2] = tf32r(kv.z);
            Ks[r * FSK + c + 3] = tf32r(kv.w);
            const float4 vv = *(const float4*)(qkv + g + vOff + c);
            Vs[r * FSV + c + 0] = tf32r(vv.x);
            Vs[r * FSV + c + 1] = tf32r(vv.y);
            Vs[r * FSV + c + 2] = tf32r(vv.z);
            Vs[r * FSV + c + 3] = tf32r(vv.w);
        }
        __syncthreads();

        if (k0 > wmax) continue;   // fully-masked tile for this warp (state unchanged)

        // ---- S = Q K^T (2 m-frags x 8 n-tiles x 8 k-steps) ----
        float sacc[2][8][4];
#pragma unroll
        for (int mt = 0; mt < 2; ++mt)
#pragma unroll
            for (int t = 0; t < 8; ++t)
                sacc[mt][t][0] = sacc[mt][t][1] = sacc[mt][t][2] = sacc[mt][t][3] = 0.f;
#pragma unroll
        for (int ks = 0; ks < 8; ++ks) {
            const int c = ks * 8 + ql;
            uint32_t qa1[4];
            qa1[0] = __float_as_uint(Qs[(rq + 16) * FSK + c]);
            qa1[1] = __float_as_uint(Qs[(rq + 24) * FSK + c]);
            qa1[2] = __float_as_uint(Qs[(rq + 16) * FSK + c + 4]);
            qa1[3] = __float_as_uint(Qs[(rq + 24) * FSK + c + 4]);
#pragma unroll
            for (int t = 0; t < 8; ++t) {
                const uint32_t b0 = __float_as_uint(Ks[(t * 8 + quad) * FSK + c]);
                const uint32_t b1 = __float_as_uint(Ks[(t * 8 + quad) * FSK + c + 4]);
                mma_tf32(sacc[0][t], qa0[ks], b0, b1);
                mma_tf32(sacc[1][t], qa1, b0, b1);
            }
        }

        // ---- scale + causal mask + row max (4 rows) ----
        float rm[4];
        rm[0] = rm[1] = rm[2] = rm[3] = -INFINITY;
#pragma unroll
        for (int mt = 0; mt < 2; ++mt)
#pragma unroll
            for (int t = 0; t < 8; ++t) {
                const int gc = k0 + t * 8 + ql * 2;
                float v0 = sacc[mt][t][0] * C2; if (gc     > qrow[2*mt])   v0 = -INFINITY;
                float v1 = sacc[mt][t][1] * C2; if (gc + 1 > qrow[2*mt])   v1 = -INFINITY;
                float v2 = sacc[mt][t][2] * C2; if (gc     > qrow[2*mt+1]) v2 = -INFINITY;
                float v3 = sacc[mt][t][3] * C2; if (gc + 1 > qrow[2*mt+1]) v3 = -INFINITY;
                sacc[mt][t][0] = v0; sacc[mt][t][1] = v1;
                sacc[mt][t][2] = v2; sacc[mt][t][3] = v3;
                rm[2*mt]   = fmaxf(rm[2*mt],   fmaxf(v0, v1));
                rm[2*mt+1] = fmaxf(rm[2*mt+1], fmaxf(v2, v3));
            }
        float mn[4], al[4];
#pragma unroll
        for (int i = 0; i < 4; ++i) {
            rm[i] = fmaxf(rm[i], __shfl_xor_sync(0xffffffffu, rm[i], 1));
            rm[i] = fmaxf(rm[i], __shfl_xor_sync(0xffffffffu, rm[i], 2));
            mn[i] = fmaxf(m[i], rm[i]);
            al[i] = exp2f(m[i] - mn[i]);
        }

        // ---- exp, P write, O rescale ----
        float sum[4];
        sum[0] = sum[1] = sum[2] = sum[3] = 0.f;
#pragma unroll
        for (int mt = 0; mt < 2; ++mt) {
            const int r0 = rq + mt * 16;
#pragma unroll
            for (int t = 0; t < 8; ++t) {
                const float p0 = exp2f(sacc[mt][t][0] - mn[2*mt]);
                const float p1 = exp2f(sacc[mt][t][1] - mn[2*mt]);
                const float p2 = exp2f(sacc[mt][t][2] - mn[2*mt+1]);
                const float p3 = exp2f(sacc[mt][t][3] - mn[2*mt+1]);
                sum[2*mt]   += p0 + p1;
                sum[2*mt+1] += p2 + p3;
                o[mt][t][0] *= al[2*mt];   o[mt][t][1] *= al[2*mt];
                o[mt][t][2] *= al[2*mt+1]; o[mt][t][3] *= al[2*mt+1];
                const int col = t * 8 + ql * 2;
                float2 w0; w0.x = tf32r(p0); w0.y = tf32r(p1);
                *(float2*)&Ps[r0 * FSK + col] = w0;
                float2 w1; w1.x = tf32r(p2); w1.y = tf32r(p3);
                *(float2*)&Ps[(r0 + 8) * FSK + col] = w1;
            }
        }
#pragma unroll
        for (int i = 0; i < 4; ++i) {
            sum[i] += __shfl_xor_sync(0xffffffffu, sum[i], 1);
            sum[i] += __shfl_xor_sync(0xffffffffu, sum[i], 2);
            l[i] = l[i] * al[i] + sum[i];
            m[i] = mn[i];
        }
        __syncwarp();   // P rows are warp-private

        // ---- O += P V ----
#pragma unroll
        for (int ks = 0; ks < 8; ++ks) {
            const int pc = ks * 8 + ql;
            uint32_t pa0[4], pa1[4];
            pa0[0] = __float_as_uint(Ps[rq * FSK + pc]);
            pa0[1] = __float_as_uint(Ps[(rq + 8) * FSK + pc]);
            pa0[2] = __float_as_uint(Ps[rq * FSK + pc + 4]);
            pa0[3] = __float_as_uint(Ps[(rq + 8) * FSK + pc + 4]);
            pa1[0] = __float_as_uint(Ps[(rq + 16) * FSK + pc]);
            pa1[1] = __float_as_uint(Ps[(rq + 24) * FSK + pc]);
            pa1[2] = __float_as_uint(Ps[(rq + 16) * FSK + pc + 4]);
            pa1[3] = __float_as_uint(Ps[(rq + 24) * FSK + pc + 4]);
#pragma unroll
            for (int t = 0; t < 8; ++t) {
                const uint32_t b0 = __float_as_uint(Vs[(ks * 8 + ql) * FSV + t * 8 + quad]);
                const uint32_t b1 = __float_as_uint(Vs[(ks * 8 + ql + 4) * FSV + t * 8 + quad]);
                mma_tf32(o[0][t], pa0, b0, b1);
                mma_tf32(o[1][t], pa1, b0, b1);
            }
        }
        __syncwarp();
    }

    // ---- epilogue: normalize and store 4 rows ----
    float inv[4];
#pragma unroll
    for (int i = 0; i < 4; ++i) inv[i] = 1.f / l[i];
#pragma unroll
    for (int mt = 0; mt < 2; ++mt)
#pragma unroll
        for (int t = 0; t < 8; ++t) {
            const int col = h * HD + t * 8 + ql * 2;
            float2 w;
            w.x = o[mt][t][0] * inv[2*mt]; w.y = o[mt][t][1] * inv[2*mt];
            *(float2*)(y + (rowBase + qrow[2*mt]) * CC + col) = w;
            w.x = o[mt][t][2] * inv[2*mt+1]; w.y = o[mt][t][3] * inv[2*mt+1];
            *(float2*)(y + (rowBase + qrow[2*mt+1]) * CC + col) = w;
        }
}

// ----------------------------------------------------------------------------
extern "C" void kernel_launch(void* const* d_in, const int* in_sizes, int n_in,
                              void* d_out, int out_size)
{
    const float *x = nullptr, *w_attn = nullptr, *b_attn = nullptr,
                *w_proj = nullptr, *b_proj = nullptr;
    for (int i = 0; i < n_in; ++i) {
        const int s = in_sizes[i];
        const float* p = (const float*)d_in[i];
        if      (s == MM * CC)   x      = p;
        else if (s == CC * NQKV) w_attn = p;
        else if (s == NQKV)      b_attn = p;
        else if (s == CC * CC)   w_proj = p;
        else if (s == CC)        b_proj = p;
    }
    float* out = (float*)d_out;

    float *qkv = nullptr, *y = nullptr;
    cudaGetSymbolAddress((void**)&qkv, g_qkv);
    cudaGetSymbolAddress((void**)&y, g_y);

    cudaFuncSetAttribute(flash_attn_tf32_kernel,
                         cudaFuncAttributeMaxDynamicSharedMemorySize,
                         (int)FA_SMEM_BYTES);

    dim3 blk(256);
    gemm_tf32_bias<<<dim3(NQKV / 128, MM / 128), blk>>>(
        x, w_attn, b_attn, qkv, MM, NQKV, CC);
    flash_attn_tf32_kernel<<<dim3(TT / 256, HH, BB), blk, FA_SMEM_BYTES>>>(qkv, y);
    gemm_tf32_bias<<<dim3(CC / 128, MM / 128), blk>>>(
        y, w_proj, b_proj, out, MM, CC, CC);
}